// round 1
// baseline (speedup 1.0000x reference)
#include <cuda_runtime.h>
#include <math.h>

#define B_    32
#define D_    768
#define NH_   12
#define HD_   64
#define L_    12
#define MLP_D 3072
#define S0_   197
#define SMAX_ 237
#define NE_   10
#define LP_   40
#define NPL_  5
#define NC_   100
#define MALL  (B_*SMAX_)   // 7584 padded rows

// -------- scratch (device globals; no runtime allocation) --------
__device__ float g_x  [MALL * D_];        // residual stream, row = b*237 + s
__device__ float g_h  [MALL * D_];        // LN output
__device__ float g_qkv[MALL * 3 * D_];    // qkv projections
__device__ float g_o  [MALL * D_];        // attention output
__device__ float g_mlp[MALL * MLP_D];     // fc1 output
__device__ float g_bp [B_ * NPL_ * LP_ * D_]; // gathered prompts

// ============================================================
// Generic tiled SGEMM: C[m,n] = (RESID? X[m,n]:0) + sum_k A[m,k]*W[k,n] + bias[n]
// ACT: 0 = none, 1 = exact GELU
// BM=BN=64, BK=16, 256 threads, 4x4 per thread.
// ============================================================
template<int ACT, bool RESID>
__global__ void gemm64(const float* __restrict__ A, const float* __restrict__ W,
                       const float* __restrict__ bias, const float* __restrict__ Xres,
                       float* __restrict__ C, int M, int N, int K)
{
    __shared__ float As[16][68];
    __shared__ float Ws[16][68];
    const int tid = threadIdx.x;
    const int m0 = blockIdx.y * 64, n0 = blockIdx.x * 64;
    const int tx = tid & 15, ty = tid >> 4;

    const int la_m = tid >> 2, la_k = (tid & 3) * 4;   // A tile loader
    const int lw_k = tid >> 4, lw_n = (tid & 15) * 4;  // W tile loader

    float acc[4][4];
#pragma unroll
    for (int i = 0; i < 4; i++)
#pragma unroll
        for (int j = 0; j < 4; j++) acc[i][j] = 0.f;

    for (int k0 = 0; k0 < K; k0 += 16) {
        float4 av = make_float4(0.f, 0.f, 0.f, 0.f);
        int gm = m0 + la_m;
        if (gm < M) av = *(const float4*)(A + (size_t)gm * K + k0 + la_k);
        As[la_k + 0][la_m] = av.x;
        As[la_k + 1][la_m] = av.y;
        As[la_k + 2][la_m] = av.z;
        As[la_k + 3][la_m] = av.w;

        float4 wv = *(const float4*)(W + (size_t)(k0 + lw_k) * N + n0 + lw_n);
        *(float4*)&Ws[lw_k][lw_n] = wv;
        __syncthreads();

#pragma unroll
        for (int kk = 0; kk < 16; kk++) {
            float4 a4 = *(const float4*)&As[kk][ty * 4];
            float4 b4 = *(const float4*)&Ws[kk][tx * 4];
            float a[4] = {a4.x, a4.y, a4.z, a4.w};
            float b[4] = {b4.x, b4.y, b4.z, b4.w};
#pragma unroll
            for (int i = 0; i < 4; i++)
#pragma unroll
                for (int j = 0; j < 4; j++) acc[i][j] += a[i] * b[j];
        }
        __syncthreads();
    }

#pragma unroll
    for (int i = 0; i < 4; i++) {
        int m = m0 + ty * 4 + i;
        if (m >= M) continue;
#pragma unroll
        for (int j = 0; j < 4; j++) {
            int n = n0 + tx * 4 + j;
            float v = acc[i][j] + bias[n];
            if (RESID) v += Xres[(size_t)m * N + n];
            if (ACT == 1) v = 0.5f * v * (1.0f + erff(v * 0.70710678118654752f));
            C[(size_t)m * N + n] = v;
        }
    }
}

// ============================================================
// Patch-embed GEMM: im2col on the fly.
// M = B*196 = 6272, N = 768, K = 768 (= 3*16*16)
// out row (b, p) -> g_x[b*237 + 1 + p] ; adds patch_b + pos_embed[1+p]
// ============================================================
__global__ void patch_embed_kernel(const float* __restrict__ inp, const float* __restrict__ pw,
                                   const float* __restrict__ pb, const float* __restrict__ pos,
                                   float* __restrict__ x)
{
    __shared__ float As[16][68];
    __shared__ float Ws[16][68];
    const int tid = threadIdx.x;
    const int m0 = blockIdx.y * 64, n0 = blockIdx.x * 64;
    const int tx = tid & 15, ty = tid >> 4;

    const int la_m = tid >> 2, la_k = (tid & 3) * 4;
    const int lw_n = tid >> 2, lw_k = (tid & 3) * 4;

    // A-row mapping (computed once)
    const int gm = m0 + la_m;
    const int ab  = gm / 196;
    const int ap  = gm % 196;
    const int apy = ap / 14, apx = ap % 14;

    float acc[4][4];
#pragma unroll
    for (int i = 0; i < 4; i++)
#pragma unroll
        for (int j = 0; j < 4; j++) acc[i][j] = 0.f;

    for (int k0 = 0; k0 < 768; k0 += 16) {
        int k = k0 + la_k;
        int c = k >> 8, ii = (k >> 4) & 15, jj = k & 15;
        const float* src = inp + (((size_t)ab * 3 + c) * 224 + (apy * 16 + ii)) * 224
                               + apx * 16 + jj;
        float4 av = *(const float4*)src;
        As[la_k + 0][la_m] = av.x;
        As[la_k + 1][la_m] = av.y;
        As[la_k + 2][la_m] = av.z;
        As[la_k + 3][la_m] = av.w;

        // W^T gather: Ws[k][n] = pw[n*768 + k]
        float4 wv = *(const float4*)(pw + (size_t)(n0 + lw_n) * 768 + k0 + lw_k);
        Ws[lw_k + 0][lw_n] = wv.x;
        Ws[lw_k + 1][lw_n] = wv.y;
        Ws[lw_k + 2][lw_n] = wv.z;
        Ws[lw_k + 3][lw_n] = wv.w;
        __syncthreads();

#pragma unroll
        for (int kk = 0; kk < 16; kk++) {
            float4 a4 = *(const float4*)&As[kk][ty * 4];
            float4 b4 = *(const float4*)&Ws[kk][tx * 4];
            float a[4] = {a4.x, a4.y, a4.z, a4.w};
            float b[4] = {b4.x, b4.y, b4.z, b4.w};
#pragma unroll
            for (int i = 0; i < 4; i++)
#pragma unroll
                for (int j = 0; j < 4; j++) acc[i][j] += a[i] * b[j];
        }
        __syncthreads();
    }

#pragma unroll
    for (int i = 0; i < 4; i++) {
        int m = m0 + ty * 4 + i;
        int bb = m / 196, pp = m % 196;
#pragma unroll
        for (int j = 0; j < 4; j++) {
            int n = n0 + tx * 4 + j;
            float v = acc[i][j] + pb[n] + pos[(size_t)(1 + pp) * 768 + n];
            x[((size_t)bb * SMAX_ + 1 + pp) * 768 + n] = v;
        }
    }
}

// ---- cls token + pos[0] ----
__global__ void cls_pos_kernel(const float* __restrict__ cls, const float* __restrict__ pos,
                               float* __restrict__ x)
{
    int i = blockIdx.x * 256 + threadIdx.x;   // B_*768 total
    int b = i / 768, d = i % 768;
    x[(size_t)b * SMAX_ * 768 + d] = cls[d] + pos[d];
}

// ---- gather prompts per expert, add pos[0,0] ----
__global__ void build_bp_kernel(const float* __restrict__ prompts, const int* __restrict__ eid,
                                const float* __restrict__ pos, float* __restrict__ bp)
{
    int i = blockIdx.x * 256 + threadIdx.x;   // B*NPL*LP*768
    int d = i % 768;
    int r = i / 768;
    int t = r % LP_; r /= LP_;
    int pl = r % NPL_;
    int b = r / NPL_;
    int e = eid[b];
    bp[i] = prompts[(((size_t)pl * NE_ + e) * LP_ + t) * 768 + d] + pos[d];
}

// ---- append prompt slice pl at rows 197..236 ----
__global__ void append_kernel(const float* __restrict__ bp, float* __restrict__ x, int pl)
{
    int i = blockIdx.x * 256 + threadIdx.x;   // B*LP*768
    int d = i % 768;
    int r = i / 768;
    int t = r % LP_;
    int b = r / LP_;
    x[((size_t)b * SMAX_ + S0_ + t) * 768 + d] =
        bp[(((size_t)b * NPL_ + pl) * LP_ + t) * 768 + d];
}

// ---- LayerNorm over dim 768, one block per row ----
__global__ void ln_kernel(const float* __restrict__ x, const float* __restrict__ s,
                          const float* __restrict__ bb, float* __restrict__ h)
{
    int row = blockIdx.x;
    int t = threadIdx.x;
    const float* xr = x + (size_t)row * 768;
    float v0 = xr[t], v1 = xr[t + 256], v2 = xr[t + 512];
    __shared__ float red[256];
    red[t] = v0 + v1 + v2;
    __syncthreads();
    for (int o = 128; o > 0; o >>= 1) { if (t < o) red[t] += red[t + o]; __syncthreads(); }
    float mean = red[0] * (1.f / 768.f);
    __syncthreads();
    float d0 = v0 - mean, d1 = v1 - mean, d2 = v2 - mean;
    red[t] = d0 * d0 + d1 * d1 + d2 * d2;
    __syncthreads();
    for (int o = 128; o > 0; o >>= 1) { if (t < o) red[t] += red[t + o]; __syncthreads(); }
    float rstd = rsqrtf(red[0] * (1.f / 768.f) + 1e-6f);
    float* hr = h + (size_t)row * 768;
    hr[t]       = d0 * rstd * s[t]       + bb[t];
    hr[t + 256] = d1 * rstd * s[t + 256] + bb[t + 256];
    hr[t + 512] = d2 * rstd * s[t + 512] + bb[t + 512];
}

// ---- fused attention: one block per (q, head, batch) ----
__global__ void attn_kernel(const float* __restrict__ qkv, float* __restrict__ o, int S)
{
    int qi = blockIdx.x, hh = blockIdx.y, b = blockIdx.z;
    int t = threadIdx.x;
    __shared__ float qs[HD_];
    __shared__ float sc[SMAX_];
    __shared__ float red[256];
    const float* base = qkv + (size_t)b * SMAX_ * 2304;

    if (t < HD_) qs[t] = base[(size_t)qi * 2304 + hh * HD_ + t];
    __syncthreads();

    if (t < S) {
        const float* kr = base + (size_t)t * 2304 + 768 + hh * HD_;
        float acc = 0.f;
#pragma unroll
        for (int d = 0; d < HD_; d++) acc += qs[d] * kr[d];
        sc[t] = acc * 0.125f;
    }
    __syncthreads();

    red[t] = (t < S) ? sc[t] : -1e30f;
    __syncthreads();
    for (int o2 = 128; o2 > 0; o2 >>= 1) { if (t < o2) red[t] = fmaxf(red[t], red[t + o2]); __syncthreads(); }
    float mx = red[0];
    __syncthreads();
    float e = (t < S) ? __expf(sc[t] - mx) : 0.f;
    red[t] = e;
    __syncthreads();
    for (int o2 = 128; o2 > 0; o2 >>= 1) { if (t < o2) red[t] += red[t + o2]; __syncthreads(); }
    float inv = 1.f / red[0];
    __syncthreads();
    if (t < S) sc[t] = e * inv;
    __syncthreads();

    if (t < HD_) {
        const float* vr = base + 1536 + hh * HD_ + t;
        float acc = 0.f;
        for (int k2 = 0; k2 < S; k2++) acc += sc[k2] * vr[(size_t)k2 * 2304];
        o[((size_t)b * SMAX_ + qi) * 768 + hh * HD_ + t] = acc;
    }
}

// ---- final LN(token 0) + expert head ----
__global__ void head_kernel(const float* __restrict__ x, const float* __restrict__ ns,
                            const float* __restrict__ nb, const int* __restrict__ eid,
                            const float* __restrict__ hw, const float* __restrict__ hb,
                            float* __restrict__ out)
{
    int b = blockIdx.x, t = threadIdx.x;
    __shared__ float feat[768];
    __shared__ float red[256];
    const float* xr = x + (size_t)b * SMAX_ * 768;
    float v0 = xr[t], v1 = xr[t + 256], v2 = xr[t + 512];
    red[t] = v0 + v1 + v2;
    __syncthreads();
    for (int o = 128; o > 0; o >>= 1) { if (t < o) red[t] += red[t + o]; __syncthreads(); }
    float mean = red[0] * (1.f / 768.f);
    __syncthreads();
    float d0 = v0 - mean, d1 = v1 - mean, d2 = v2 - mean;
    red[t] = d0 * d0 + d1 * d1 + d2 * d2;
    __syncthreads();
    for (int o = 128; o > 0; o >>= 1) { if (t < o) red[t] += red[t + o]; __syncthreads(); }
    float rstd = rsqrtf(red[0] * (1.f / 768.f) + 1e-6f);
    feat[t]       = d0 * rstd * ns[t]       + nb[t];
    feat[t + 256] = d1 * rstd * ns[t + 256] + nb[t + 256];
    feat[t + 512] = d2 * rstd * ns[t + 512] + nb[t + 512];
    __syncthreads();

    int e = eid[b];
    if (t < NC_) {
        float acc = hb[(size_t)e * NC_ + t];
        const float* w = hw + (size_t)e * 768 * NC_ + t;
        for (int d = 0; d < 768; d++) acc += feat[d] * w[(size_t)d * NC_];
        out[(size_t)b * NC_ + t] = acc;
    }
}

// ============================================================
extern "C" void kernel_launch(void* const* d_in, const int* in_sizes, int n_in,
                              void* d_out, int out_size)
{
    const float* inputs  = (const float*)d_in[0];
    const int*   eids    = (const int*)  d_in[1];
    const float* patch_w = (const float*)d_in[2];
    const float* patch_b = (const float*)d_in[3];
    const float* cls     = (const float*)d_in[4];
    const float* pos     = (const float*)d_in[5];
    const float* ln1_s   = (const float*)d_in[6];
    const float* ln1_b   = (const float*)d_in[7];
    const float* qkv_w   = (const float*)d_in[8];
    const float* qkv_b   = (const float*)d_in[9];
    const float* proj_w  = (const float*)d_in[10];
    const float* proj_b  = (const float*)d_in[11];
    const float* ln2_s   = (const float*)d_in[12];
    const float* ln2_b   = (const float*)d_in[13];
    const float* fc1_w   = (const float*)d_in[14];
    const float* fc1_b   = (const float*)d_in[15];
    const float* fc2_w   = (const float*)d_in[16];
    const float* fc2_b   = (const float*)d_in[17];
    const float* norm_s  = (const float*)d_in[18];
    const float* norm_b  = (const float*)d_in[19];
    const float* prompts = (const float*)d_in[20];
    const float* head_w  = (const float*)d_in[21];
    const float* head_b  = (const float*)d_in[22];
    float* out = (float*)d_out;

    float *x, *h, *qkv, *o, *mlp, *bp;
    cudaGetSymbolAddress((void**)&x,   g_x);
    cudaGetSymbolAddress((void**)&h,   g_h);
    cudaGetSymbolAddress((void**)&qkv, g_qkv);
    cudaGetSymbolAddress((void**)&o,   g_o);
    cudaGetSymbolAddress((void**)&mlp, g_mlp);
    cudaGetSymbolAddress((void**)&bp,  g_bp);

    // patch embed + cls + prompts
    patch_embed_kernel<<<dim3(12, 98), 256>>>(inputs, patch_w, patch_b, pos, x);
    cls_pos_kernel<<<(B_ * 768) / 256, 256>>>(cls, pos, x);
    build_bp_kernel<<<(B_ * NPL_ * LP_ * 768) / 256, 256>>>(prompts, eids, pos, bp);

    const int gy = (MALL + 63) / 64;   // 119
    for (int i = 0; i < L_; i++) {
        int S = (i < NPL_) ? SMAX_ : S0_;
        if (i < NPL_)
            append_kernel<<<(B_ * LP_ * 768) / 256, 256>>>(bp, x, i);

        ln_kernel<<<MALL, 256>>>(x, ln1_s + (size_t)i * D_, ln1_b + (size_t)i * D_, h);
        gemm64<0, false><<<dim3(36, gy), 256>>>(h, qkv_w + (size_t)i * D_ * 3 * D_,
                                                qkv_b + (size_t)i * 3 * D_, nullptr, qkv,
                                                MALL, 3 * D_, D_);
        attn_kernel<<<dim3(S, NH_, B_), 256>>>(qkv, o, S);
        gemm64<0, true><<<dim3(12, gy), 256>>>(o, proj_w + (size_t)i * D_ * D_,
                                               proj_b + (size_t)i * D_, x, x,
                                               MALL, D_, D_);
        ln_kernel<<<MALL, 256>>>(x, ln2_s + (size_t)i * D_, ln2_b + (size_t)i * D_, h);
        gemm64<1, false><<<dim3(48, gy), 256>>>(h, fc1_w + (size_t)i * D_ * MLP_D,
                                                fc1_b + (size_t)i * MLP_D, nullptr, mlp,
                                                MALL, MLP_D, D_);
        gemm64<0, true><<<dim3(12, gy), 256>>>(mlp, fc2_w + (size_t)i * MLP_D * D_,
                                               fc2_b + (size_t)i * D_, x, x,
                                               MALL, D_, MLP_D);
    }

    head_kernel<<<B_, 256>>>(x, norm_s, norm_b, eids, head_w, head_b, out);
}